// round 16
// baseline (speedup 1.0000x reference)
#include <cuda_runtime.h>
#include <cuda_bf16.h>
#include <cstdint>

// Problem constants
#define NB  4
#define NN  4096   // H*W
#define NC  256
#define NCP 128

// Scratch (static __device__ arrays: the sanctioned no-alloc scratch mechanism).
static __device__ float          g_V  [NB * NN * NCP];       // fp32 V
static __device__ __nv_bfloat16  g_Khi[NB * NN * NCP];       // K split hi/lo  [b*NN+n][c]
static __device__ __nv_bfloat16  g_Klo[NB * NN * NCP];
static __device__ __nv_bfloat16  g_Qhi[NB * NN * NCP];       // Q split hi/lo
static __device__ __nv_bfloat16  g_Qlo[NB * NN * NCP];
static __device__ __nv_bfloat16  g_Vthi[NB * NCP * NN];      // V^T hi/lo  [b*NCP+c][n]
static __device__ __nv_bfloat16  g_Vtlo[NB * NCP * NN];
static __device__ __nv_bfloat16  g_Wth[4 * NCP * NC];        // W^T splits [sel][col][k]
static __device__ __nv_bfloat16  g_Wtl[4 * NCP * NC];

// ---- bf16 split + pack helpers ----
__device__ __forceinline__ void bsplit(float x, __nv_bfloat16& h, __nv_bfloat16& l) {
    h = __float2bfloat16(x);
    l = __float2bfloat16(x - __bfloat162float(h));
}
__device__ __forceinline__ uint32_t pk(__nv_bfloat16 a, __nv_bfloat16 b) {
    return (uint32_t)__bfloat16_as_ushort(a) | ((uint32_t)__bfloat16_as_ushort(b) << 16);
}
__device__ __forceinline__ uint32_t pkhi(float a, float b) {
    return pk(__float2bfloat16(a), __float2bfloat16(b));
}
__device__ __forceinline__ uint32_t pklo(float a, float b) {
    __nv_bfloat16 ha = __float2bfloat16(a), hb = __float2bfloat16(b);
    return pk(__float2bfloat16(a - __bfloat162float(ha)),
              __float2bfloat16(b - __bfloat162float(hb)));
}

// ---- warp MMA: m16n8k16, row.col, bf16 in, fp32 acc (baseline PTX, sm_80+) ----
__device__ __forceinline__ void mma_bf16(float c[4], uint32_t a0, uint32_t a1,
                                         uint32_t a2, uint32_t a3,
                                         uint32_t b0, uint32_t b1) {
    asm volatile("mma.sync.aligned.m16n8k16.row.col.f32.bf16.bf16.f32 "
        "{%0,%1,%2,%3}, {%4,%5,%6,%7}, {%8,%9}, {%0,%1,%2,%3};"
        : "+f"(c[0]), "+f"(c[1]), "+f"(c[2]), "+f"(c[3])
        : "r"(a0), "r"(a1), "r"(a2), "r"(a3), "r"(b0), "r"(b1));
}

// ---- ldmatrix x4 (baseline PTX, sm_75+) ----
__device__ __forceinline__ void ldsm_x4(uint32_t& r0, uint32_t& r1,
                                        uint32_t& r2, uint32_t& r3, uint32_t addr) {
    asm volatile("ldmatrix.sync.aligned.m8n8.x4.shared.b16 {%0,%1,%2,%3}, [%4];"
        : "=r"(r0), "=r"(r1), "=r"(r2), "=r"(r3) : "r"(addr));
}
__device__ __forceinline__ uint32_t smem_u32(const void* p) {
    uint32_t a;
    asm("{ .reg .u64 t; cvta.to.shared.u64 t, %1; cvt.u32.u64 %0, t; }" : "=r"(a) : "l"(p));
    return a;
}

#define SKS 72   // 64-wide tile stride (bf16): row 144B = 4-bank shift, LDSM conflict-free
#define KS2 136  // 128-wide tile stride: row 272B = 4-bank shift, LDSM conflict-free

// ============================================================================
// Kernel 0: pre-split + transpose weights.
// ============================================================================
__global__ void wsplit_kernel(const float* __restrict__ Wk, const float* __restrict__ Wq,
                              const float* __restrict__ Wv, const float* __restrict__ Ws)
{
    const int sel = blockIdx.x;
    const float* W = (sel == 0) ? Wk : (sel == 1) ? Wq : (sel == 2) ? Wv : Ws;
    for (int idx = threadIdx.x; idx < NCP * NC; idx += blockDim.x) {
        int c = idx >> 8, k = idx & 255;
        __nv_bfloat16 h, l; bsplit(W[(size_t)k * NCP + c], h, l);
        g_Wth[sel * NCP * NC + idx] = h;
        g_Wtl[sel * NCP * NC + idx] = l;
    }
}

// ============================================================================
// Kernel 1: projections via bf16 mma 3-product split (unchanged).
// ============================================================================
#define PRJ_SMEM (4 * 128 * SKS * 2)   // 73728 B

__global__ void __launch_bounds__(256) proj_kernel(
    const float* __restrict__ X,
    const float* __restrict__ bk, const float* __restrict__ bq,
    const float* __restrict__ bv, const float* __restrict__ bs,
    float* __restrict__ OutS)
{
    extern __shared__ __align__(16) char smraw[];
    __nv_bfloat16* sXh = (__nv_bfloat16*)smraw;
    __nv_bfloat16* sXl = sXh + 128 * SKS;
    __nv_bfloat16* sWh = sXl + 128 * SKS;
    __nv_bfloat16* sWl = sWh + 128 * SKS;

    const int sel = blockIdx.y;
    const float* bia = (sel == 0) ? bk : (sel == 1) ? bq : (sel == 2) ? bv : bs;
    const __nv_bfloat16* Wh = g_Wth + sel * NCP * NC;
    const __nv_bfloat16* Wl = g_Wtl + sel * NCP * NC;

    const int tid = threadIdx.x;
    const int lane = tid & 31, w = tid >> 5;
    const int g = lane >> 2, q4 = lane & 3;
    const int wm = w & 1, wn = w >> 1;
    const int rowBase = blockIdx.x * 128;

    float C[4][4][4];
#pragma unroll
    for (int mi = 0; mi < 4; mi++)
#pragma unroll
        for (int ni = 0; ni < 4; ni++)
#pragma unroll
            for (int e = 0; e < 4; e++) C[mi][ni][e] = 0.f;

    for (int kp = 0; kp < 4; kp++) {
        __syncthreads();
#pragma unroll
        for (int u = 0; u < 8; u++) {
            int idx = tid + u * 256;
            int r = idx >> 4, c4 = idx & 15;
            float4 v = *(const float4*)(X + (size_t)(rowBase + r) * NC + kp * 64 + c4 * 4);
            __nv_bfloat16 h0,l0,h1,l1,h2,l2,h3,l3;
            bsplit(v.x,h0,l0); bsplit(v.y,h1,l1); bsplit(v.z,h2,l2); bsplit(v.w,h3,l3);
            int so = r * SKS + c4 * 4;
            *(uint2*)(sXh + so) = make_uint2(pk(h0,h1), pk(h2,h3));
            *(uint2*)(sXl + so) = make_uint2(pk(l0,l1), pk(l2,l3));
        }
#pragma unroll
        for (int u = 0; u < 4; u++) {
            int idx = tid + u * 256;
            int col = idx >> 3, k8 = idx & 7;
            int go = col * NC + kp * 64 + k8 * 8;
            int so = col * SKS + k8 * 8;
            *(uint4*)(sWh + so) = *(const uint4*)(Wh + go);
            *(uint4*)(sWl + so) = *(const uint4*)(Wl + go);
        }
        __syncthreads();

#pragma unroll
        for (int kc = 0; kc < 4; kc++) {
            const int k0 = kc * 16 + q4 * 2;
            uint32_t Bh[4][2], Bl[4][2];
#pragma unroll
            for (int ni = 0; ni < 4; ni++) {
                int col = wn * 32 + ni * 8 + g;
                Bh[ni][0] = *(const uint32_t*)(sWh + col * SKS + k0);
                Bh[ni][1] = *(const uint32_t*)(sWh + col * SKS + k0 + 8);
                Bl[ni][0] = *(const uint32_t*)(sWl + col * SKS + k0);
                Bl[ni][1] = *(const uint32_t*)(sWl + col * SKS + k0 + 8);
            }
#pragma unroll
            for (int mi = 0; mi < 4; mi++) {
                int row = wm * 64 + mi * 16 + g;
                uint32_t a0 = *(const uint32_t*)(sXh + row * SKS + k0);
                uint32_t a1 = *(const uint32_t*)(sXh + (row + 8) * SKS + k0);
                uint32_t a2 = *(const uint32_t*)(sXh + row * SKS + k0 + 8);
                uint32_t a3 = *(const uint32_t*)(sXh + (row + 8) * SKS + k0 + 8);
                uint32_t l0 = *(const uint32_t*)(sXl + row * SKS + k0);
                uint32_t l1 = *(const uint32_t*)(sXl + (row + 8) * SKS + k0);
                uint32_t l2 = *(const uint32_t*)(sXl + row * SKS + k0 + 8);
                uint32_t l3 = *(const uint32_t*)(sXl + (row + 8) * SKS + k0 + 8);
#pragma unroll
                for (int ni = 0; ni < 4; ni++)
                    mma_bf16(C[mi][ni], a0, a1, a2, a3, Bh[ni][0], Bh[ni][1]); // hh
#pragma unroll
                for (int ni = 0; ni < 4; ni++)
                    mma_bf16(C[mi][ni], a0, a1, a2, a3, Bl[ni][0], Bl[ni][1]); // hl
#pragma unroll
                for (int ni = 0; ni < 4; ni++)
                    mma_bf16(C[mi][ni], l0, l1, l2, l3, Bh[ni][0], Bh[ni][1]); // lh
            }
        }
    }

#pragma unroll
    for (int ni = 0; ni < 4; ni++) {
        int col = wn * 32 + ni * 8 + q4 * 2;
        float2 bb = *(const float2*)(bia + col);
#pragma unroll
        for (int mi = 0; mi < 4; mi++) {
            int row = rowBase + wm * 64 + mi * 16 + g;
            float v0 = C[mi][ni][0] + bb.x, v1 = C[mi][ni][1] + bb.y;
            float v2 = C[mi][ni][2] + bb.x, v3 = C[mi][ni][3] + bb.y;
            size_t o0 = (size_t)row * NCP + col;
            size_t o1 = (size_t)(row + 8) * NCP + col;
            if (sel <= 1) {
                __nv_bfloat16* Yh = (sel == 0) ? g_Khi : g_Qhi;
                __nv_bfloat16* Yl = (sel == 0) ? g_Klo : g_Qlo;
                __nv_bfloat16 h0,l0,h1,l1;
                bsplit(v0,h0,l0); bsplit(v1,h1,l1);
                *(uint32_t*)(Yh + o0) = pk(h0,h1);
                *(uint32_t*)(Yl + o0) = pk(l0,l1);
                bsplit(v2,h0,l0); bsplit(v3,h1,l1);
                *(uint32_t*)(Yh + o1) = pk(h0,h1);
                *(uint32_t*)(Yl + o1) = pk(l0,l1);
            } else {
                float* Yf = (sel == 2) ? g_V : OutS;
                *(float2*)(Yf + o0) = make_float2(v0, v1);
                *(float2*)(Yf + o1) = make_float2(v2, v3);
            }
        }
    }
}

// ============================================================================
// Kernel 2: V -> V^T bf16 hi/lo.
// ============================================================================
__global__ void vt_kernel()
{
    __shared__ float t[32][33];
    const int b  = blockIdx.z;
    const int n0 = blockIdx.x * 32;
    const int c0 = blockIdx.y * 32;
    const int tx = threadIdx.x, ty = threadIdx.y;   // 32 x 8
#pragma unroll
    for (int u = 0; u < 4; u++)
        t[ty * 4 + u][tx] = g_V[((size_t)b * NN + n0 + ty * 4 + u) * NCP + c0 + tx];
    __syncthreads();
#pragma unroll
    for (int u = 0; u < 4; u++) {
        float x = t[tx][ty * 4 + u];
        __nv_bfloat16 h, l; bsplit(x, h, l);
        size_t off = ((size_t)b * NCP + c0 + ty * 4 + u) * NN + n0 + tx;
        g_Vthi[off] = h;
        g_Vtlo[off] = l;
    }
}

// ============================================================================
// Kernel 3: FUSED flash attention (R15 + Vh-fragment caching in PV).
//   PV per ks: two halves of 4 col-pairs; Vh frags ldmatrix'd ONCE (16 regs),
//   used by both PhVh and PlVh passes; Vl streamed per-j. 24 -> 16 ldsm.x4
//   per ks. Accumulator order per Co unchanged -> bit-identical results.
// ============================================================================
#define FL_SMEM ((4 * 64 * KS2 + 2 * 128 * SKS) * 2)   // 106496 B

__global__ void __launch_bounds__(128) flash_kernel(float* __restrict__ Out)
{
    extern __shared__ __align__(16) char smraw[];
    __nv_bfloat16* sKh = (__nv_bfloat16*)smraw;          // [64][KS2]
    __nv_bfloat16* sKl = sKh + 64 * KS2;
    __nv_bfloat16* sQh = sKl + 64 * KS2;                 // [64][KS2]
    __nv_bfloat16* sQl = sQh + 64 * KS2;
    __nv_bfloat16* sVh = sQl + 64 * KS2;                 // [128][SKS]
    __nv_bfloat16* sVl = sVh + 128 * SKS;

    const int tid = threadIdx.x;
    const int lane = tid & 31, w = tid >> 5;             // 4 warps
    const int g = lane >> 2, t = lane & 3;
    const int l7 = lane & 7, q = lane >> 3;              // ldmatrix lane decomposition
    const int mt = blockIdx.x, b = blockIdx.y;

    // ---- load K tile once (64 rows x 128 d, hi+lo) ----
#pragma unroll
    for (int u = 0; u < 8; u++) {
        int idx = tid + u * 128;
        int r = idx >> 4, c8 = idx & 15;
        size_t go = ((size_t)(b * NN + mt * 64 + r)) * NCP + c8 * 8;
        int so = r * KS2 + c8 * 8;
        *(uint4*)(sKh + so) = *(const uint4*)(g_Khi + go);
        *(uint4*)(sKl + so) = *(const uint4*)(g_Klo + go);
    }

    const int rowA = w * 16 + g;

    const uint32_t aOff = (uint32_t)((w * 16 + l7 + (q & 1) * 8) * (KS2 * 2) + (q >> 1) * 16);
    const uint32_t addrAh = smem_u32(sKh) + aOff;
    const uint32_t addrAl = smem_u32(sKl) + aOff;
    const uint32_t bOffQ = (uint32_t)((l7 + (q >> 1) * 8) * (KS2 * 2) + (q & 1) * 16);
    const uint32_t addrQh = smem_u32(sQh) + bOffQ;
    const uint32_t addrQl = smem_u32(sQl) + bOffQ;
    const uint32_t bOffV = (uint32_t)((l7 + (q >> 1) * 8) * (SKS * 2) + (q & 1) * 16);
    const uint32_t addrVh = smem_u32(sVh) + bOffV;
    const uint32_t addrVl = smem_u32(sVl) + bOffV;

    float Co[16][4];
#pragma unroll
    for (int ci = 0; ci < 16; ci++)
#pragma unroll
        for (int e = 0; e < 4; e++) Co[ci][e] = 0.f;
    float m0 = -1e30f, m1 = -1e30f, l0s = 0.f, l1s = 0.f;

    for (int ch = 0; ch < NN / 64; ch++) {
        __syncthreads();
        // Q chunk: 64 q-rows x 128 d
#pragma unroll
        for (int u = 0; u < 8; u++) {
            int idx = tid + u * 128;
            int r = idx >> 4, c8 = idx & 15;
            size_t go = ((size_t)(b * NN + ch * 64 + r)) * NCP + c8 * 8;
            int so = r * KS2 + c8 * 8;
            *(uint4*)(sQh + so) = *(const uint4*)(g_Qhi + go);
            *(uint4*)(sQl + so) = *(const uint4*)(g_Qlo + go);
        }
        // V chunk: 128 c'-rows x 64 n
#pragma unroll
        for (int u = 0; u < 8; u++) {
            int idx = tid + u * 128;
            int r = idx >> 3, c8 = idx & 7;
            size_t go = ((size_t)(b * NCP + r)) * NN + ch * 64 + c8 * 8;
            int so = r * SKS + c8 * 8;
            *(uint4*)(sVh + so) = *(const uint4*)(g_Vthi + go);
            *(uint4*)(sVl + so) = *(const uint4*)(g_Vtlo + go);
        }
        __syncthreads();

        // ---- S tile: passes hh (cache bh) -> lh (cached) -> hl ----
        float Cs[8][4];
#pragma unroll
        for (int ni = 0; ni < 8; ni++)
#pragma unroll
            for (int e = 0; e < 4; e++) Cs[ni][e] = 0.f;
#pragma unroll
        for (int kc = 0; kc < 8; kc++) {
            const uint32_t k32 = kc * 32;
            uint32_t a0, a1, a2, a3, e0, e1, e2, e3;
            ldsm_x4(a0, a1, a2, a3, addrAh + k32);
            ldsm_x4(e0, e1, e2, e3, addrAl + k32);
            uint32_t bhr[4][4];
#pragma unroll
            for (int np = 0; np < 4; np++) {                       // hh + cache bh
                ldsm_x4(bhr[np][0], bhr[np][1], bhr[np][2], bhr[np][3],
                        addrQh + np * (16 * KS2 * 2) + k32);
                mma_bf16(Cs[2*np],   a0, a1, a2, a3, bhr[np][0], bhr[np][1]);
                mma_bf16(Cs[2*np+1], a0, a1, a2, a3, bhr[np][2], bhr[np][3]);
            }
#pragma unroll
            for (int np = 0; np < 4; np++) {                       // lh (cached bh)
                mma_bf16(Cs[2*np],   e0, e1, e2, e3, bhr[np][0], bhr[np][1]);
                mma_bf16(Cs[2*np+1], e0, e1, e2, e3, bhr[np][2], bhr[np][3]);
            }
#pragma unroll
            for (int np = 0; np < 4; np++) {                       // hl
                uint32_t b0, b1, b2, b3;
                ldsm_x4(b0, b1, b2, b3, addrQl + np * (16 * KS2 * 2) + k32);
                mma_bf16(Cs[2*np],   a0, a1, a2, a3, b0, b1);
                mma_bf16(Cs[2*np+1], a0, a1, a2, a3, b2, b3);
            }
        }

        // ---- online softmax (rows g and g+8; row spread over 4 t-lanes) ----
        float mx0 = -1e30f, mx1 = -1e30f;
#pragma unroll
        for (int ni = 0; ni < 8; ni++) {
            mx0 = fmaxf(mx0, fmaxf(Cs[ni][0], Cs[ni][1]));
            mx1 = fmaxf(mx1, fmaxf(Cs[ni][2], Cs[ni][3]));
        }
        mx0 = fmaxf(mx0, __shfl_xor_sync(0xffffffffu, mx0, 1));
        mx0 = fmaxf(mx0, __shfl_xor_sync(0xffffffffu, mx0, 2));
        mx1 = fmaxf(mx1, __shfl_xor_sync(0xffffffffu, mx1, 1));
        mx1 = fmaxf(mx1, __shfl_xor_sync(0xffffffffu, mx1, 2));
        float mn0 = fmaxf(m0, mx0), mn1 = fmaxf(m1, mx1);
        if (mn0 > m0 || mn1 > m1) {
            float al0 = __expf(m0 - mn0), al1 = __expf(m1 - mn1);
            l0s *= al0; l1s *= al1;
#pragma unroll
            for (int ci = 0; ci < 16; ci++) {
                Co[ci][0] *= al0; Co[ci][1] *= al0;
                Co[ci][2] *= al1; Co[ci][3] *= al1;
            }
            m0 = mn0; m1 = mn1;
        }
        float s0 = 0.f, s1 = 0.f;
#pragma unroll
        for (int ni = 0; ni < 8; ni++) {
            Cs[ni][0] = __expf(Cs[ni][0] - m0);
            Cs[ni][1] = __expf(Cs[ni][1] - m0);
            Cs[ni][2] = __expf(Cs[ni][2] - m1);
            Cs[ni][3] = __expf(Cs[ni][3] - m1);
            s0 += Cs[ni][0] + Cs[ni][1];
            s1 += Cs[ni][2] + Cs[ni][3];
        }
        s0 += __shfl_xor_sync(0xffffffffu, s0, 1);
        s0 += __shfl_xor_sync(0xffffffffu, s0, 2);
        s1 += __shfl_xor_sync(0xffffffffu, s1, 1);
        s1 += __shfl_xor_sync(0xffffffffu, s1, 2);
        l0s += s0;
        l1s += s1;

        // ---- build P A-frags (C-frag == A-frag identity) ----
        uint32_t Ph[4][4], Pl[4][4];
#pragma unroll
        for (int ki = 0; ki < 4; ki++) {
            Ph[ki][0] = pkhi(Cs[2*ki  ][0], Cs[2*ki  ][1]);
            Ph[ki][1] = pkhi(Cs[2*ki  ][2], Cs[2*ki  ][3]);
            Ph[ki][2] = pkhi(Cs[2*ki+1][0], Cs[2*ki+1][1]);
            Ph[ki][3] = pkhi(Cs[2*ki+1][2], Cs[2*ki+1][3]);
            Pl[ki][0] = pklo(Cs[2*ki  ][0], Cs[2*ki  ][1]);
            Pl[ki][1] = pklo(Cs[2*ki  ][2], Cs[2*ki  ][3]);
            Pl[ki][2] = pklo(Cs[2*ki+1][0], Cs[2*ki+1][1]);
            Pl[ki][3] = pklo(Cs[2*ki+1][2], Cs[2*ki+1][3]);
        }

        // ---- O += P @ V: halves of 4 col-pairs, Vh frags cached ----
#pragma unroll
        for (int ks = 0; ks < 4; ks++) {
            const uint32_t k32 = ks * 32;
#pragma unroll
            for (int hf = 0; hf < 2; hf++) {
                uint32_t vh[4][4];
#pragma unroll
                for (int j = 0; j < 4; j++)                        // load Vh once
                    ldsm_x4(vh[j][0], vh[j][1], vh[j][2], vh[j][3],
                            addrVh + (hf * 4 + j) * (16 * SKS * 2) + k32);
#pragma unroll
                for (int j = 0; j < 4; j++) {                      // PhVh
                    int ci = (hf * 4 + j) * 2;
                    mma_bf16(Co[ci],   Ph[ks][0], Ph[ks][1], Ph[ks][2], Ph[ks][3], vh[j][0], vh[j][1]);
                    mma_bf16(Co[ci+1], Ph[ks][0], Ph[ks][1], Ph[ks][2], Ph[ks][3], vh[j][2], vh[j][3]);
                }
#pragma unroll
                for (int j = 0; j < 4; j++) {                      // PhVl (stream Vl)
                    int ci = (hf * 4 + j) * 2;
                    uint32_t v0, v1, v2, v3;
                    ldsm_x4(v0, v1, v2, v3, addrVl + (hf * 4 + j) * (16 * SKS * 2) + k32);
                    mma_bf16(Co[ci],   Ph[ks][0], Ph[ks][1], Ph[ks][2], Ph[ks][3], v0, v1);
                    mma_bf16(Co[ci+1], Ph[ks][0], Ph[ks][1], Ph[ks][2], Ph[ks][3], v2, v3);
                }
#pragma unroll
                for (int j = 0; j < 4; j++) {                      // PlVh (cached Vh)
                    int ci = (hf * 4 + j) * 2;
                    mma_bf16(Co[ci],   Pl[ks][0], Pl[ks][1], Pl[ks][2], Pl[ks][3], vh[j][0], vh[j][1]);
                    mma_bf16(Co[ci+1], Pl[ks][0], Pl[ks][1], Pl[ks][2], Pl[ks][3], vh[j][2], vh[j][3]);
                }
            }
        }
    }

    // ---- epilogue: Out = O/l + shortcut (Out holds shortcut) ----
    float i0 = 1.0f / l0s, i1 = 1.0f / l1s;
    size_t r0 = (size_t)(b * NN + mt * 64 + rowA) * NCP;
    size_t r1 = (size_t)(b * NN + mt * 64 + rowA + 8) * NCP;
#pragma unroll
    for (int ci = 0; ci < 16; ci++) {
        int col = ci * 8 + t * 2;
        float2 s0v = *(float2*)(Out + r0 + col);
        float2 s1v = *(float2*)(Out + r1 + col);
        *(float2*)(Out + r0 + col) = make_float2(Co[ci][0] * i0 + s0v.x,
                                                 Co[ci][1] * i0 + s0v.y);
        *(float2*)(Out + r1 + col) = make_float2(Co[ci][2] * i1 + s1v.x,
                                                 Co[ci][3] * i1 + s1v.y);
    }
}

// ============================================================================
// Launch
// ============================================================================
extern "C" void kernel_launch(void* const* d_in, const int* in_sizes, int n_in,
                              void* d_out, int out_size) {
    (void)in_sizes; (void)n_in; (void)out_size;
    const float* x  = (const float*)d_in[0];
    const float* Wk = (const float*)d_in[1];
    const float* bk = (const float*)d_in[2];
    const float* Wq = (const float*)d_in[3];
    const float* bq = (const float*)d_in[4];
    const float* Wv = (const float*)d_in[5];
    const float* bv = (const float*)d_in[6];
    const float* Ws = (const float*)d_in[7];
    const float* bs = (const float*)d_in[8];
    float* out = (float*)d_out;

    cudaFuncSetAttribute(proj_kernel,  cudaFuncAttributeMaxDynamicSharedMemorySize, PRJ_SMEM);
    cudaFuncSetAttribute(flash_kernel, cudaFuncAttributeMaxDynamicSharedMemorySize, FL_SMEM);

    // 0) weight pre-split
    wsplit_kernel<<<4, 256>>>(Wk, Wq, Wv, Ws);
    // 1) projections: K/Q hi-lo, V f32, shortcut -> d_out
    proj_kernel<<<dim3(NB * NN / 128, 4), 256, PRJ_SMEM>>>(x, bk, bq, bv, bs, out);
    // 2) V -> V^T bf16 hi/lo
    vt_kernel<<<dim3(NN / 32, NCP / 32, NB), dim3(32, 8)>>>();
    // 3) fused flash attention (+ shortcut add)
    flash_kernel<<<dim3(NN / 64, NB), 128, FL_SMEM>>>(out);
}

// round 17
// speedup vs baseline: 1.0548x; 1.0548x over previous
#include <cuda_runtime.h>
#include <cuda_bf16.h>
#include <cstdint>

// Problem constants
#define NB  4
#define NN  4096   // H*W
#define NC  256
#define NCP 128

// Scratch (static __device__ arrays: the sanctioned no-alloc scratch mechanism).
static __device__ float          g_V  [NB * NN * NCP];       // fp32 V
static __device__ __nv_bfloat16  g_Khi[NB * NN * NCP];       // K split hi/lo  [b*NN+n][c]
static __device__ __nv_bfloat16  g_Klo[NB * NN * NCP];
static __device__ __nv_bfloat16  g_Qhi[NB * NN * NCP];       // Q split hi/lo
static __device__ __nv_bfloat16  g_Qlo[NB * NN * NCP];
static __device__ __nv_bfloat16  g_Vthi[NB * NCP * NN];      // V^T hi/lo  [b*NCP+c][n]
static __device__ __nv_bfloat16  g_Vtlo[NB * NCP * NN];
static __device__ __nv_bfloat16  g_Wth[4 * NCP * NC];        // W^T splits [sel][col][k]
static __device__ __nv_bfloat16  g_Wtl[4 * NCP * NC];

// ---- bf16 split + pack helpers ----
__device__ __forceinline__ void bsplit(float x, __nv_bfloat16& h, __nv_bfloat16& l) {
    h = __float2bfloat16(x);
    l = __float2bfloat16(x - __bfloat162float(h));
}
__device__ __forceinline__ uint32_t pk(__nv_bfloat16 a, __nv_bfloat16 b) {
    return (uint32_t)__bfloat16_as_ushort(a) | ((uint32_t)__bfloat16_as_ushort(b) << 16);
}
__device__ __forceinline__ uint32_t pkhi(float a, float b) {
    return pk(__float2bfloat16(a), __float2bfloat16(b));
}
__device__ __forceinline__ uint32_t pklo(float a, float b) {
    __nv_bfloat16 ha = __float2bfloat16(a), hb = __float2bfloat16(b);
    return pk(__float2bfloat16(a - __bfloat162float(ha)),
              __float2bfloat16(b - __bfloat162float(hb)));
}

// ---- warp MMA: m16n8k16, row.col, bf16 in, fp32 acc (baseline PTX, sm_80+) ----
__device__ __forceinline__ void mma_bf16(float c[4], uint32_t a0, uint32_t a1,
                                         uint32_t a2, uint32_t a3,
                                         uint32_t b0, uint32_t b1) {
    asm volatile("mma.sync.aligned.m16n8k16.row.col.f32.bf16.bf16.f32 "
        "{%0,%1,%2,%3}, {%4,%5,%6,%7}, {%8,%9}, {%0,%1,%2,%3};"
        : "+f"(c[0]), "+f"(c[1]), "+f"(c[2]), "+f"(c[3])
        : "r"(a0), "r"(a1), "r"(a2), "r"(a3), "r"(b0), "r"(b1));
}

// ---- ldmatrix x4 + cp.async (baseline PTX, sm_75+/sm_80+) ----
__device__ __forceinline__ void ldsm_x4(uint32_t& r0, uint32_t& r1,
                                        uint32_t& r2, uint32_t& r3, uint32_t addr) {
    asm volatile("ldmatrix.sync.aligned.m8n8.x4.shared.b16 {%0,%1,%2,%3}, [%4];"
        : "=r"(r0), "=r"(r1), "=r"(r2), "=r"(r3) : "r"(addr));
}
__device__ __forceinline__ uint32_t smem_u32(const void* p) {
    uint32_t a;
    asm("{ .reg .u64 t; cvta.to.shared.u64 t, %1; cvt.u32.u64 %0, t; }" : "=r"(a) : "l"(p));
    return a;
}
__device__ __forceinline__ void cpa16(uint32_t saddr, const void* g) {
    asm volatile("cp.async.cg.shared.global [%0], [%1], 16;" :: "r"(saddr), "l"(g));
}
#define CPA_COMMIT() asm volatile("cp.async.commit_group;" ::: "memory")
#define CPA_WAIT0()  asm volatile("cp.async.wait_group 0;" ::: "memory")

#define SKS 72   // 64-wide tile stride (bf16): row 144B = 4-bank shift, LDSM conflict-free
#define KS2 136  // 128-wide tile stride: row 272B = 4-bank shift, LDSM conflict-free

// ============================================================================
// Kernel 0: pre-split + transpose weights.
// ============================================================================
__global__ void wsplit_kernel(const float* __restrict__ Wk, const float* __restrict__ Wq,
                              const float* __restrict__ Wv, const float* __restrict__ Ws)
{
    const int sel = blockIdx.x;
    const float* W = (sel == 0) ? Wk : (sel == 1) ? Wq : (sel == 2) ? Wv : Ws;
    for (int idx = threadIdx.x; idx < NCP * NC; idx += blockDim.x) {
        int c = idx >> 8, k = idx & 255;
        __nv_bfloat16 h, l; bsplit(W[(size_t)k * NCP + c], h, l);
        g_Wth[sel * NCP * NC + idx] = h;
        g_Wtl[sel * NCP * NC + idx] = l;
    }
}

// ============================================================================
// Kernel 1: projections via bf16 mma 3-product split (unchanged).
// ============================================================================
#define PRJ_SMEM (4 * 128 * SKS * 2)   // 73728 B

__global__ void __launch_bounds__(256) proj_kernel(
    const float* __restrict__ X,
    const float* __restrict__ bk, const float* __restrict__ bq,
    const float* __restrict__ bv, const float* __restrict__ bs,
    float* __restrict__ OutS)
{
    extern __shared__ __align__(16) char smraw[];
    __nv_bfloat16* sXh = (__nv_bfloat16*)smraw;
    __nv_bfloat16* sXl = sXh + 128 * SKS;
    __nv_bfloat16* sWh = sXl + 128 * SKS;
    __nv_bfloat16* sWl = sWh + 128 * SKS;

    const int sel = blockIdx.y;
    const float* bia = (sel == 0) ? bk : (sel == 1) ? bq : (sel == 2) ? bv : bs;
    const __nv_bfloat16* Wh = g_Wth + sel * NCP * NC;
    const __nv_bfloat16* Wl = g_Wtl + sel * NCP * NC;

    const int tid = threadIdx.x;
    const int lane = tid & 31, w = tid >> 5;
    const int g = lane >> 2, q4 = lane & 3;
    const int wm = w & 1, wn = w >> 1;
    const int rowBase = blockIdx.x * 128;

    float C[4][4][4];
#pragma unroll
    for (int mi = 0; mi < 4; mi++)
#pragma unroll
        for (int ni = 0; ni < 4; ni++)
#pragma unroll
            for (int e = 0; e < 4; e++) C[mi][ni][e] = 0.f;

    for (int kp = 0; kp < 4; kp++) {
        __syncthreads();
#pragma unroll
        for (int u = 0; u < 8; u++) {
            int idx = tid + u * 256;
            int r = idx >> 4, c4 = idx & 15;
            float4 v = *(const float4*)(X + (size_t)(rowBase + r) * NC + kp * 64 + c4 * 4);
            __nv_bfloat16 h0,l0,h1,l1,h2,l2,h3,l3;
            bsplit(v.x,h0,l0); bsplit(v.y,h1,l1); bsplit(v.z,h2,l2); bsplit(v.w,h3,l3);
            int so = r * SKS + c4 * 4;
            *(uint2*)(sXh + so) = make_uint2(pk(h0,h1), pk(h2,h3));
            *(uint2*)(sXl + so) = make_uint2(pk(l0,l1), pk(l2,l3));
        }
#pragma unroll
        for (int u = 0; u < 4; u++) {
            int idx = tid + u * 256;
            int col = idx >> 3, k8 = idx & 7;
            int go = col * NC + kp * 64 + k8 * 8;
            int so = col * SKS + k8 * 8;
            *(uint4*)(sWh + so) = *(const uint4*)(Wh + go);
            *(uint4*)(sWl + so) = *(const uint4*)(Wl + go);
        }
        __syncthreads();

#pragma unroll
        for (int kc = 0; kc < 4; kc++) {
            const int k0 = kc * 16 + q4 * 2;
            uint32_t Bh[4][2], Bl[4][2];
#pragma unroll
            for (int ni = 0; ni < 4; ni++) {
                int col = wn * 32 + ni * 8 + g;
                Bh[ni][0] = *(const uint32_t*)(sWh + col * SKS + k0);
                Bh[ni][1] = *(const uint32_t*)(sWh + col * SKS + k0 + 8);
                Bl[ni][0] = *(const uint32_t*)(sWl + col * SKS + k0);
                Bl[ni][1] = *(const uint32_t*)(sWl + col * SKS + k0 + 8);
            }
#pragma unroll
            for (int mi = 0; mi < 4; mi++) {
                int row = wm * 64 + mi * 16 + g;
                uint32_t a0 = *(const uint32_t*)(sXh + row * SKS + k0);
                uint32_t a1 = *(const uint32_t*)(sXh + (row + 8) * SKS + k0);
                uint32_t a2 = *(const uint32_t*)(sXh + row * SKS + k0 + 8);
                uint32_t a3 = *(const uint32_t*)(sXh + (row + 8) * SKS + k0 + 8);
                uint32_t l0 = *(const uint32_t*)(sXl + row * SKS + k0);
                uint32_t l1 = *(const uint32_t*)(sXl + (row + 8) * SKS + k0);
                uint32_t l2 = *(const uint32_t*)(sXl + row * SKS + k0 + 8);
                uint32_t l3 = *(const uint32_t*)(sXl + (row + 8) * SKS + k0 + 8);
#pragma unroll
                for (int ni = 0; ni < 4; ni++)
                    mma_bf16(C[mi][ni], a0, a1, a2, a3, Bh[ni][0], Bh[ni][1]); // hh
#pragma unroll
                for (int ni = 0; ni < 4; ni++)
                    mma_bf16(C[mi][ni], a0, a1, a2, a3, Bl[ni][0], Bl[ni][1]); // hl
#pragma unroll
                for (int ni = 0; ni < 4; ni++)
                    mma_bf16(C[mi][ni], l0, l1, l2, l3, Bh[ni][0], Bh[ni][1]); // lh
            }
        }
    }

#pragma unroll
    for (int ni = 0; ni < 4; ni++) {
        int col = wn * 32 + ni * 8 + q4 * 2;
        float2 bb = *(const float2*)(bia + col);
#pragma unroll
        for (int mi = 0; mi < 4; mi++) {
            int row = rowBase + wm * 64 + mi * 16 + g;
            float v0 = C[mi][ni][0] + bb.x, v1 = C[mi][ni][1] + bb.y;
            float v2 = C[mi][ni][2] + bb.x, v3 = C[mi][ni][3] + bb.y;
            size_t o0 = (size_t)row * NCP + col;
            size_t o1 = (size_t)(row + 8) * NCP + col;
            if (sel <= 1) {
                __nv_bfloat16* Yh = (sel == 0) ? g_Khi : g_Qhi;
                __nv_bfloat16* Yl = (sel == 0) ? g_Klo : g_Qlo;
                __nv_bfloat16 h0,l0,h1,l1;
                bsplit(v0,h0,l0); bsplit(v1,h1,l1);
                *(uint32_t*)(Yh + o0) = pk(h0,h1);
                *(uint32_t*)(Yl + o0) = pk(l0,l1);
                bsplit(v2,h0,l0); bsplit(v3,h1,l1);
                *(uint32_t*)(Yh + o1) = pk(h0,h1);
                *(uint32_t*)(Yl + o1) = pk(l0,l1);
            } else {
                float* Yf = (sel == 2) ? g_V : OutS;
                *(float2*)(Yf + o0) = make_float2(v0, v1);
                *(float2*)(Yf + o1) = make_float2(v2, v3);
            }
        }
    }
}

// ============================================================================
// Kernel 2: V -> V^T bf16 hi/lo.
// ============================================================================
__global__ void vt_kernel()
{
    __shared__ float t[32][33];
    const int b  = blockIdx.z;
    const int n0 = blockIdx.x * 32;
    const int c0 = blockIdx.y * 32;
    const int tx = threadIdx.x, ty = threadIdx.y;   // 32 x 8
#pragma unroll
    for (int u = 0; u < 4; u++)
        t[ty * 4 + u][tx] = g_V[((size_t)b * NN + n0 + ty * 4 + u) * NCP + c0 + tx];
    __syncthreads();
#pragma unroll
    for (int u = 0; u < 4; u++) {
        float x = t[tx][ty * 4 + u];
        __nv_bfloat16 h, l; bsplit(x, h, l);
        size_t off = ((size_t)b * NCP + c0 + ty * 4 + u) * NN + n0 + tx;
        g_Vthi[off] = h;
        g_Vtlo[off] = l;
    }
}

// ============================================================================
// Kernel 3: FUSED flash attention — R15 compute structure (proven 324.6us),
//   tile loads converted to cp.async pipelining:
//     Q(ch+1) flies under PV(ch); V(ch+1) flies under S(ch+1)+softmax.
//   Same 2 barriers per chunk; each wait_group lands after >1000 cyc of mma.
//   Bytes and per-accumulator mma order identical -> bit-identical results.
// ============================================================================
#define FL_SMEM ((4 * 64 * KS2 + 2 * 128 * SKS) * 2)   // 106496 B

__global__ void __launch_bounds__(128) flash_kernel(float* __restrict__ Out)
{
    extern __shared__ __align__(16) char smraw[];
    __nv_bfloat16* sKh = (__nv_bfloat16*)smraw;          // [64][KS2]
    __nv_bfloat16* sKl = sKh + 64 * KS2;
    __nv_bfloat16* sQh = sKl + 64 * KS2;                 // [64][KS2]
    __nv_bfloat16* sQl = sQh + 64 * KS2;
    __nv_bfloat16* sVh = sQl + 64 * KS2;                 // [128][SKS]
    __nv_bfloat16* sVl = sVh + 128 * SKS;

    const int tid = threadIdx.x;
    const int lane = tid & 31, w = tid >> 5;             // 4 warps
    const int g = lane >> 2, t = lane & 3;
    const int l7 = lane & 7, q = lane >> 3;              // ldmatrix lane decomposition
    const int mt = blockIdx.x, b = blockIdx.y;

    const uint32_t uQh = smem_u32(sQh), uQl = smem_u32(sQl);
    const uint32_t uVh = smem_u32(sVh), uVl = smem_u32(sVl);

    // per-thread cp.async slot assignments (fixed across chunks)
    const int qR = tid >> 4, qC8 = tid & 15;             // Q: 2 rows per thread (u stride 8)
    const int vR = tid >> 3, vC8 = tid & 7;              // V: 8 rows per thread? (u stride 16)

    // ---- load K tile once (64 rows x 128 d, hi+lo) ----
#pragma unroll
    for (int u = 0; u < 8; u++) {
        int idx = tid + u * 128;
        int r = idx >> 4, c8 = idx & 15;
        size_t go = ((size_t)(b * NN + mt * 64 + r)) * NCP + c8 * 8;
        int so = r * KS2 + c8 * 8;
        *(uint4*)(sKh + so) = *(const uint4*)(g_Khi + go);
        *(uint4*)(sKl + so) = *(const uint4*)(g_Klo + go);
    }

    // ---- prologue: async-fill Q(0) and V(0) ----
    {
#pragma unroll
        for (int u = 0; u < 8; u++) {
            int r = qR + u * 8;
            size_t go = ((size_t)(b * NN + r)) * NCP + qC8 * 8;
            uint32_t so2 = (uint32_t)(r * KS2 + qC8 * 8) * 2;
            cpa16(uQh + so2, g_Qhi + go);
            cpa16(uQl + so2, g_Qlo + go);
        }
#pragma unroll
        for (int u = 0; u < 8; u++) {
            int r = vR + u * 16;
            size_t go = ((size_t)(b * NCP + r)) * NN + vC8 * 8;
            uint32_t so2 = (uint32_t)(r * SKS + vC8 * 8) * 2;
            cpa16(uVh + so2, g_Vthi + go);
            cpa16(uVl + so2, g_Vtlo + go);
        }
        CPA_COMMIT();
        CPA_WAIT0();
    }
    __syncthreads();

    const int rowA = w * 16 + g;

    const uint32_t aOff = (uint32_t)((w * 16 + l7 + (q & 1) * 8) * (KS2 * 2) + (q >> 1) * 16);
    const uint32_t addrAh = smem_u32(sKh) + aOff;
    const uint32_t addrAl = smem_u32(sKl) + aOff;
    const uint32_t bOffQ = (uint32_t)((l7 + (q >> 1) * 8) * (KS2 * 2) + (q & 1) * 16);
    const uint32_t addrQh = uQh + bOffQ;
    const uint32_t addrQl = uQl + bOffQ;
    const uint32_t bOffV = (uint32_t)((l7 + (q >> 1) * 8) * (SKS * 2) + (q & 1) * 16);
    const uint32_t addrVh = uVh + bOffV;
    const uint32_t addrVl = uVl + bOffV;

    float Co[16][4];
#pragma unroll
    for (int ci = 0; ci < 16; ci++)
#pragma unroll
        for (int e = 0; e < 4; e++) Co[ci][e] = 0.f;
    float m0 = -1e30f, m1 = -1e30f, l0s = 0.f, l1s = 0.f;

    for (int ch = 0; ch < NN / 64; ch++) {
        // ---- S tile: passes hh (cache bh) -> lh (cached) -> hl ----
        float Cs[8][4];
#pragma unroll
        for (int ni = 0; ni < 8; ni++)
#pragma unroll
            for (int e = 0; e < 4; e++) Cs[ni][e] = 0.f;
#pragma unroll
        for (int kc = 0; kc < 8; kc++) {
            const uint32_t k32 = kc * 32;
            uint32_t a0, a1, a2, a3, e0, e1, e2, e3;
            ldsm_x4(a0, a1, a2, a3, addrAh + k32);
            ldsm_x4(e0, e1, e2, e3, addrAl + k32);
            uint32_t bhr[4][4];
#pragma unroll
            for (int np = 0; np < 4; np++) {                       // hh + cache bh
                ldsm_x4(bhr[np][0], bhr[np][1], bhr[np][2], bhr[np][3],
                        addrQh + np * (16 * KS2 * 2) + k32);
                mma_bf16(Cs[2*np],   a0, a1, a2, a3, bhr[np][0], bhr[np][1]);
                mma_bf16(Cs[2*np+1], a0, a1, a2, a3, bhr[np][2], bhr[np][3]);
            }
#pragma unroll
            for (int np = 0; np < 4; np++) {                       // lh (cached bh)
                mma_bf16(Cs[2*np],   e0, e1, e2, e3, bhr[np][0], bhr[np][1]);
                mma_bf16(Cs[2*np+1], e0, e1, e2, e3, bhr[np][2], bhr[np][3]);
            }
#pragma unroll
            for (int np = 0; np < 4; np++) {                       // hl
                uint32_t b0, b1, b2, b3;
                ldsm_x4(b0, b1, b2, b3, addrQl + np * (16 * KS2 * 2) + k32);
                mma_bf16(Cs[2*np],   a0, a1, a2, a3, b0, b1);
                mma_bf16(Cs[2*np+1], a0, a1, a2, a3, b2, b3);
            }
        }

        // ---- online softmax (rows g and g+8; row spread over 4 t-lanes) ----
        float mx0 = -1e30f, mx1 = -1e30f;
#pragma unroll
        for (int ni = 0; ni < 8; ni++) {
            mx0 = fmaxf(mx0, fmaxf(Cs[ni][0], Cs[ni][1]));
            mx1 = fmaxf(mx1, fmaxf(Cs[ni][2], Cs[ni][3]));
        }
        mx0 = fmaxf(mx0, __shfl_xor_sync(0xffffffffu, mx0, 1));
        mx0 = fmaxf(mx0, __shfl_xor_sync(0xffffffffu, mx0, 2));
        mx1 = fmaxf(mx1, __shfl_xor_sync(0xffffffffu, mx1, 1));
        mx1 = fmaxf(mx1, __shfl_xor_sync(0xffffffffu, mx1, 2));
        float mn0 = fmaxf(m0, mx0), mn1 = fmaxf(m1, mx1);
        if (mn0 > m0 || mn1 > m1) {
            float al0 = __expf(m0 - mn0), al1 = __expf(m1 - mn1);
            l0s *= al0; l1s *= al1;
#pragma unroll
            for (int ci = 0; ci < 16; ci++) {
                Co[ci][0] *= al0; Co[ci][1] *= al0;
                Co[ci][2] *= al1; Co[ci][3] *= al1;
            }
            m0 = mn0; m1 = mn1;
        }
        float s0 = 0.f, s1 = 0.f;
#pragma unroll
        for (int ni = 0; ni < 8; ni++) {
            Cs[ni][0] = __expf(Cs[ni][0] - m0);
            Cs[ni][1] = __expf(Cs[ni][1] - m0);
            Cs[ni][2] = __expf(Cs[ni][2] - m1);
            Cs[ni][3] = __expf(Cs[ni][3] - m1);
            s0 += Cs[ni][0] + Cs[ni][1];
            s1 += Cs[ni][2] + Cs[ni][3];
        }
        s0 += __shfl_xor_sync(0xffffffffu, s0, 1);
        s0 += __shfl_xor_sync(0xffffffffu, s0, 2);
        s1 += __shfl_xor_sync(0xffffffffu, s1, 1);
        s1 += __shfl_xor_sync(0xffffffffu, s1, 2);
        l0s += s0;
        l1s += s1;

        // ---- V(ch) arrived long ago; barrier: Q consumed + V visible ----
        CPA_WAIT0();
        __syncthreads();
        // ---- issue Q(ch+1): flies under PV(ch) ----
        if (ch + 1 < NN / 64) {
#pragma unroll
            for (int u = 0; u < 8; u++) {
                int r = qR + u * 8;
                size_t go = ((size_t)(b * NN + (ch + 1) * 64 + r)) * NCP + qC8 * 8;
                uint32_t so2 = (uint32_t)(r * KS2 + qC8 * 8) * 2;
                cpa16(uQh + so2, g_Qhi + go);
                cpa16(uQl + so2, g_Qlo + go);
            }
            CPA_COMMIT();
        }

        // ---- build P A-frags (C-frag == A-frag identity) ----
        uint32_t Ph[4][4], Pl[4][4];
#pragma unroll
        for (int ki = 0; ki < 4; ki++) {
            Ph[ki][0] = pkhi(Cs[2*ki  ][0], Cs[2*ki  ][1]);
            Ph[ki][1] = pkhi(Cs[2*ki  ][2], Cs[2*ki  ][3]);
            Ph[ki][2] = pkhi(Cs[2*ki+1][0], Cs[2*ki+1][1]);
            Ph[ki][3] = pkhi(Cs[2*ki+1][2], Cs[2*ki+1][3]);
            Pl[ki][0] = pklo(Cs[2*ki  ][0], Cs[2*ki  ][1]);
            Pl[ki][1] = pklo(Cs[2*ki  ][2], Cs[2*ki  ][3]);
            Pl[ki][2] = pklo(Cs[2*ki+1][0], Cs[2*ki+1][1]);
            Pl[ki][3] = pklo(Cs[2*ki+1][2], Cs[2*ki+1][3]);
        }

        // ---- O += P @ V: product-outer passes (R15 form) ----
#pragma unroll
        for (int ks = 0; ks < 4; ks++) {
            const uint32_t k32 = ks * 32;
#pragma unroll
            for (int cp = 0; cp < 8; cp++) {                       // PhVh
                uint32_t v0, v1, v2, v3;
                ldsm_x4(v0, v1, v2, v3, addrVh + cp * (16 * SKS * 2) + k32);
                mma_bf16(Co[2*cp],   Ph[ks][0], Ph[ks][1], Ph[ks][2], Ph[ks][3], v0, v1);
                mma_bf16(Co[2*cp+1], Ph[ks][0], Ph[ks][1], Ph[ks][2], Ph[ks][3], v2, v3);
            }
#pragma unroll
            for (int cp = 0; cp < 8; cp++) {                       // PhVl
                uint32_t v0, v1, v2, v3;
                ldsm_x4(v0, v1, v2, v3, addrVl + cp * (16 * SKS * 2) + k32);
                mma_bf16(Co[2*cp],   Ph[ks][0], Ph[ks][1], Ph[ks][2], Ph[ks][3], v0, v1);
                mma_bf16(Co[2*cp+1], Ph[ks][0], Ph[ks][1], Ph[ks][2], Ph[ks][3], v2, v3);
            }
#pragma unroll
            for (int cp = 0; cp < 8; cp++) {                       // PlVh
                uint32_t v0, v1, v2, v3;
                ldsm_x4(v0, v1, v2, v3, addrVh + cp * (16 * SKS * 2) + k32);
                mma_bf16(Co[2*cp],   Pl[ks][0], Pl[ks][1], Pl[ks][2], Pl[ks][3], v0, v1);
                mma_bf16(Co[2*cp+1], Pl[ks][0], Pl[ks][1], Pl[ks][2], Pl[ks][3], v2, v3);
            }
        }

        // ---- Q(ch+1) arrived under PV; barrier: V consumed + Q visible ----
        CPA_WAIT0();
        __syncthreads();
        // ---- issue V(ch+1): flies under S(ch+1)+softmax ----
        if (ch + 1 < NN / 64) {
#pragma unroll
            for (int u = 0; u < 8; u++) {
                int r = vR + u * 16;
                size_t go = ((size_t)(b * NCP + r)) * NN + (ch + 1) * 64 + vC8 * 8;
                uint32_t so2 = (uint32_t)(r * SKS + vC8 * 8) * 2;
                cpa16(uVh + so2, g_Vthi + go);
                cpa16(uVl + so2, g_Vtlo + go);
            }
            CPA_COMMIT();
        }
    }

    // ---- epilogue: Out = O/l + shortcut (Out holds shortcut) ----
    float i0 = 1.0f / l0s, i1 = 1.0f / l1s;
    size_t r0 = (size_t)(b * NN + mt * 64 + rowA) * NCP;
    size_t r1 = (size_t)(b * NN + mt * 64 + rowA + 8) * NCP;
#pragma unroll
    for (int ci = 0; ci < 16; ci++) {
        int col = ci * 8 + t * 2;
        float2 s0v = *(float2*)(Out + r0 + col);
        float2 s1v = *(float2*)(Out + r1 + col);
        *(float2*)(Out + r0 + col) = make_float2(Co[ci][0] * i0 + s0v.x,
                                                 Co[ci][1] * i0 + s0v.y);
        *(float2*)(Out + r1 + col) = make_float2(Co[ci][2] * i1 + s1v.x,
                                                 Co[ci][3] * i1 + s1v.y);
    }
}

// ============================================================================
// Launch
// ============================================================================
extern "C" void kernel_launch(void* const* d_in, const int* in_sizes, int n_in,
                              void* d_out, int out_size) {
    (void)in_sizes; (void)n_in; (void)out_size;
    const float* x  = (const float*)d_in[0];
    const float* Wk = (const float*)d_in[1];
    const float* bk = (const float*)d_in[2];
    const float* Wq = (const float*)d_in[3];
    const float* bq = (const float*)d_in[4];
    const float* Wv = (const float*)d_in[5];
    const float* bv = (const float*)d_in[6];
    const float* Ws = (const float*)d_in[7];
    const float* bs = (const float*)d_in[8];
    float* out = (float*)d_out;

    cudaFuncSetAttribute(proj_kernel,  cudaFuncAttributeMaxDynamicSharedMemorySize, PRJ_SMEM);
    cudaFuncSetAttribute(flash_kernel, cudaFuncAttributeMaxDynamicSharedMemorySize, FL_SMEM);

    // 0) weight pre-split
    wsplit_kernel<<<4, 256>>>(Wk, Wq, Wv, Ws);
    // 1) projections: K/Q hi-lo, V f32, shortcut -> d_out
    proj_kernel<<<dim3(NB * NN / 128, 4), 256, PRJ_SMEM>>>(x, bk, bq, bv, bs, out);
    // 2) V -> V^T bf16 hi/lo
    vt_kernel<<<dim3(NN / 32, NCP / 32, NB), dim3(32, 8)>>>();
    // 3) fused flash attention (+ shortcut add), cp.async-pipelined
    flash_kernel<<<dim3(NN / 64, NB), 128, FL_SMEM>>>(out);
}